// round 6
// baseline (speedup 1.0000x reference)
#include <cuda_runtime.h>

// LSTM_22763326669221 — fused big-batch tiny-LSTM, round 6.
// R5: 1431us, L1(shared)=83.6% binding, fma=50%. Fix: 2 batch elements
// per thread so each broadcast weight LDS feeds 2x FFMA2 -> shared
// traffic per FLOP halves, FMA pipe becomes the wall (~600us floor).

#define SEQB  3
#define BATCH 524288
#define INPD  2
#define HIDD  32
#define NCLS  2
#define FOUT  3

#define THREADS 128
#define EPT    2                 // elements per thread
#define ESTRIDE (BATCH / EPT)    // 262144

typedef unsigned long long u64;

__device__ __forceinline__ u64 ffma2(u64 a, u64 b, u64 c) {
    u64 d;
    asm("fma.rn.f32x2 %0, %1, %2, %3;" : "=l"(d) : "l"(a), "l"(b), "l"(c));
    return d;
}
__device__ __forceinline__ u64 pk(float lo, float hi) {
    u64 r;
    asm("mov.b64 %0, {%1, %2};" : "=l"(r) : "f"(lo), "f"(hi));
    return r;
}
__device__ __forceinline__ void upk(u64 v, float& lo, float& hi) {
    asm("mov.b64 {%0, %1}, %2;" : "=f"(lo), "=f"(hi) : "l"(v));
}
// Opaque pass-through: result treated as fresh each call (anti-LICM).
__device__ __forceinline__ unsigned launder(unsigned a) {
    asm volatile("" : "+r"(a));
    return a;
}
// 16B shared load — plain (reorderable/pipelinable).
__device__ __forceinline__ void lds2(u64& a, u64& b, unsigned addr) {
    asm("ld.shared.v2.b64 {%0, %1}, [%2];"
        : "=l"(a), "=l"(b) : "r"(addr));
}
__device__ __forceinline__ u64 lds1(unsigned addr) {
    u64 v;
    asm("ld.shared.b64 %0, [%1];" : "=l"(v) : "r"(addr));
    return v;
}
__device__ __forceinline__ float ex2f(float x) {
    float r; asm("ex2.approx.f32 %0, %1;" : "=f"(r) : "f"(x)); return r;
}
__device__ __forceinline__ float rcpf(float x) {
    float r; asm("rcp.approx.f32 %0, %1;" : "=f"(r) : "f"(x)); return r;
}
__device__ __forceinline__ float sigmoidf(float x) {
    float t = ex2f(-1.4426950408889634f * x);
    return rcpf(1.0f + t);
}
__device__ __forceinline__ float tanhf_(float x) {
    float u = ex2f(-2.8853900817779268f * x);
    float r = rcpf(1.0f + u);
    return fmaf(-u, r, r);
}

// Shared layouts (u64 pair-packed, even/odd hidden units):
//  sW [p][kp][r], r = gate*2+par (gates i,f,g,o), row j = gate*32+2p+par
//  sIn[p][r][s] : s=0 -> (W_ih[j][0], W_ih[j][1]) ; s=1 -> (b[j], 0)
//  sFC[n][kp]   : (W_fc[n][2kp], W_fc[n][2kp+1]);  sFCb[n] = (b_fc[n], 0)

__global__ void __launch_bounds__(THREADS, 1)
lstm_fused_kernel(const float* __restrict__ x,
                  const float* __restrict__ W_ih,
                  const float* __restrict__ W_hh,
                  const float* __restrict__ b_ih,
                  const float* __restrict__ b_hh,
                  const float* __restrict__ W_fc,
                  const float* __restrict__ b_fc,
                  float* __restrict__ out) {
    __shared__ __align__(16) u64 sW[16 * 16 * 8];
    __shared__ __align__(16) u64 sIn[16 * 8 * 2];
    __shared__ __align__(16) u64 sFC[2 * 16];
    __shared__ __align__(16) u64 sFCb[2];

    for (int i = threadIdx.x; i < 16 * 16 * 8; i += THREADS) {
        int r = i & 7, kp = (i >> 3) & 15, p = i >> 7;
        int j = (r >> 1) * 32 + 2 * p + (r & 1);
        sW[i] = pk(W_hh[j * 32 + 2 * kp], W_hh[j * 32 + 2 * kp + 1]);
    }
    for (int i = threadIdx.x; i < 16 * 8 * 2; i += THREADS) {
        int s = i & 1, r = (i >> 1) & 7, p = i >> 4;
        int j = (r >> 1) * 32 + 2 * p + (r & 1);
        sIn[i] = s ? pk(b_ih[j] + b_hh[j], 0.0f)
                   : pk(W_ih[2 * j], W_ih[2 * j + 1]);
    }
    for (int i = threadIdx.x; i < 32; i += THREADS) {
        int n = i >> 4, kp = i & 15;
        sFC[i] = pk(W_fc[n * 32 + 2 * kp], W_fc[n * 32 + 2 * kp + 1]);
    }
    if (threadIdx.x < 2) sFCb[threadIdx.x] = pk(b_fc[threadIdx.x], 0.0f);
    __syncthreads();

    const unsigned sW_a  = (unsigned)__cvta_generic_to_shared(sW);
    const unsigned sIn_a = (unsigned)__cvta_generic_to_shared(sIn);
    const unsigned sFC_a = (unsigned)__cvta_generic_to_shared(sFC);
    const unsigned sFCb_a = (unsigned)__cvta_generic_to_shared(sFCb);

    const int e0 = blockIdx.x * THREADS + threadIdx.x;  // first element

    const float2* x2 = reinterpret_cast<const float2*>(x);
    u64 d0[EPT], d1[EPT], d2[EPT];
#pragma unroll
    for (int u = 0; u < EPT; u++) {
        int e = e0 + u * ESTRIDE;
        float2 v0 = x2[0 * BATCH + e];
        float2 v1 = x2[1 * BATCH + e];
        float2 v2 = x2[2 * BATCH + e];
        d0[u] = pk(v0.x, v0.y);
        d1[u] = pk(v1.x, v1.y);
        d2[u] = pk(v2.x, v2.y);
    }

    u64 h2[EPT][16], hn[EPT][16], c2[EPT][16];
#pragma unroll
    for (int u = 0; u < EPT; u++)
#pragma unroll
        for (int k = 0; k < 16; k++) { h2[u][k] = 0ull; c2[u][k] = 0ull; }

    float2* o2 = reinterpret_cast<float2*>(out);

#pragma unroll 1
    for (int f = 0; f < FOUT; f++) {
#pragma unroll 1
        for (int t = 0; t < SEQB; t++) {
            // Fresh base addresses each step (blocks LICM/CSE across steps).
            const unsigned wA = launder(sW_a);
            const unsigned iA = launder(sIn_a);
            u64 xp[EPT];
#pragma unroll
            for (int u = 0; u < EPT; u++)
                xp[u] = (t == 0) ? d0[u] : ((t == 1) ? d1[u] : d2[u]);
#pragma unroll
            for (int p = 0; p < 16; p++) {
                const unsigned wbase = wA + p * 1024;
                const unsigned ibase = iA + p * 128;
                u64 a[EPT][8];
                // accumulator init: lane.x = x0*wih0 + b ; lane.y = x1*wih1
#pragma unroll
                for (int r = 0; r < 8; r += 2) {
                    u64 wiha, biasa, wihb, biasb;
                    lds2(wiha, biasa, ibase + r * 16);
                    lds2(wihb, biasb, ibase + r * 16 + 16);
#pragma unroll
                    for (int u = 0; u < EPT; u++) {
                        a[u][r]     = ffma2(xp[u], wiha, biasa);
                        a[u][r + 1] = ffma2(xp[u], wihb, biasb);
                    }
                }
#pragma unroll
                for (int kp = 0; kp < 16; kp++) {
                    const unsigned ka = wbase + kp * 64;
                    u64 w0, w1, w2, w3;
                    lds2(w0, w1, ka);
                    lds2(w2, w3, ka + 16);
#pragma unroll
                    for (int u = 0; u < EPT; u++) {
                        u64 hh = h2[u][kp];
                        a[u][0] = ffma2(hh, w0, a[u][0]);
                        a[u][1] = ffma2(hh, w1, a[u][1]);
                        a[u][2] = ffma2(hh, w2, a[u][2]);
                        a[u][3] = ffma2(hh, w3, a[u][3]);
                    }
                    lds2(w0, w1, ka + 32);
                    lds2(w2, w3, ka + 48);
#pragma unroll
                    for (int u = 0; u < EPT; u++) {
                        u64 hh = h2[u][kp];
                        a[u][4] = ffma2(hh, w0, a[u][4]);
                        a[u][5] = ffma2(hh, w1, a[u][5]);
                        a[u][6] = ffma2(hh, w2, a[u][6]);
                        a[u][7] = ffma2(hh, w3, a[u][7]);
                    }
                }
#pragma unroll
                for (int u = 0; u < EPT; u++) {
                    float lo, hi;
                    upk(a[u][0], lo, hi); float gi0 = sigmoidf(lo + hi);
                    upk(a[u][1], lo, hi); float gi1 = sigmoidf(lo + hi);
                    upk(a[u][2], lo, hi); float gf0 = sigmoidf(lo + hi);
                    upk(a[u][3], lo, hi); float gf1 = sigmoidf(lo + hi);
                    upk(a[u][4], lo, hi); float gg0 = tanhf_(lo + hi);
                    upk(a[u][5], lo, hi); float gg1 = tanhf_(lo + hi);
                    upk(a[u][6], lo, hi); float go0 = sigmoidf(lo + hi);
                    upk(a[u][7], lo, hi); float go1 = sigmoidf(lo + hi);
                    float c0, c1;
                    upk(c2[u][p], c0, c1);
                    float cn0 = fmaf(gf0, c0, gi0 * gg0);
                    float cn1 = fmaf(gf1, c1, gi1 * gg1);
                    c2[u][p] = pk(cn0, cn1);
                    hn[u][p] = pk(go0 * tanhf_(cn0), go1 * tanhf_(cn1));
                }
            }
#pragma unroll
            for (int u = 0; u < EPT; u++)
#pragma unroll
                for (int k = 0; k < 16; k++) h2[u][k] = hn[u][k];
        }
        // FC head: out[n] = b_fc[n] + h . W_fc[n]
        const unsigned fA  = launder(sFC_a);
        const unsigned fbA = launder(sFCb_a);
        u64 acc0[EPT], acc1[EPT];
#pragma unroll
        for (int u = 0; u < EPT; u++) {
            acc0[u] = lds1(fbA);
            acc1[u] = lds1(fbA + 8);
        }
#pragma unroll
        for (int kp = 0; kp < 16; kp += 2) {
            u64 w0, w1, w2, w3;
            lds2(w0, w1, fA + kp * 8);
            lds2(w2, w3, fA + 128 + kp * 8);
#pragma unroll
            for (int u = 0; u < EPT; u++) {
                acc0[u] = ffma2(h2[u][kp], w0, acc0[u]);
                acc0[u] = ffma2(h2[u][kp + 1], w1, acc0[u]);
                acc1[u] = ffma2(h2[u][kp], w2, acc1[u]);
                acc1[u] = ffma2(h2[u][kp + 1], w3, acc1[u]);
            }
        }
#pragma unroll
        for (int u = 0; u < EPT; u++) {
            float p0, q0, p1, q1;
            upk(acc0[u], p0, q0);
            upk(acc1[u], p1, q1);
            float out0 = p0 + q0;
            float out1 = p1 + q1;
            o2[f * BATCH + e0 + u * ESTRIDE] = make_float2(out0, out1);
            // window update: data <- [data[2], data[1], output]
            d0[u] = d2[u];
            d2[u] = pk(out0, out1);
        }
    }
}

extern "C" void kernel_launch(void* const* d_in, const int* in_sizes, int n_in,
                              void* d_out, int out_size) {
    const float* x    = (const float*)d_in[0];
    const float* W_ih = (const float*)d_in[1];
    const float* W_hh = (const float*)d_in[2];
    const float* b_ih = (const float*)d_in[3];
    const float* b_hh = (const float*)d_in[4];
    const float* W_fc = (const float*)d_in[5];
    const float* b_fc = (const float*)d_in[6];
    float* out = (float*)d_out;

    dim3 grid(BATCH / (THREADS * EPT));
    lstm_fused_kernel<<<grid, THREADS>>>(x, W_ih, W_hh, b_ih, b_hh, W_fc, b_fc, out);
}

// round 7
// speedup vs baseline: 1.3645x; 1.3645x over previous
#include <cuda_runtime.h>

// LSTM_22763326669221 — fused big-batch tiny-LSTM, round 7.
// R5 (best, 1431us): LDS-bound (L1=83.6%). R6 (EPT=2) spilled at 255 regs.
// R7: unit-split lane pairing. Lanes L and L^16 cooperate: each computes
// HALF the hidden units for TWO elements. Weight LDS per FLOP halves
// (R6's goal) at ~128 regs of state (vs R6's 192): h full (2x16 pairs),
// c+hn own-half only. Partner h-half arrives via shfl.bfly(16) per step.

#define SEQB  3
#define BATCH 524288
#define INPD  2
#define HIDD  32
#define NCLS  2
#define FOUT  3

#define THREADS 128

typedef unsigned long long u64;

__device__ __forceinline__ u64 ffma2(u64 a, u64 b, u64 c) {
    u64 d;
    asm("fma.rn.f32x2 %0, %1, %2, %3;" : "=l"(d) : "l"(a), "l"(b), "l"(c));
    return d;
}
__device__ __forceinline__ u64 pk(float lo, float hi) {
    u64 r;
    asm("mov.b64 %0, {%1, %2};" : "=l"(r) : "f"(lo), "f"(hi));
    return r;
}
__device__ __forceinline__ void upk(u64 v, float& lo, float& hi) {
    asm("mov.b64 {%0, %1}, %2;" : "=f"(lo), "=f"(hi) : "l"(v));
}
// Opaque pass-through (anti-LICM across time steps).
__device__ __forceinline__ unsigned launder(unsigned a) {
    asm volatile("" : "+r"(a));
    return a;
}
// 16B shared load — plain (reorderable/pipelinable).
__device__ __forceinline__ void lds2(u64& a, u64& b, unsigned addr) {
    asm("ld.shared.v2.b64 {%0, %1}, [%2];"
        : "=l"(a), "=l"(b) : "r"(addr));
}
__device__ __forceinline__ u64 lds1(unsigned addr) {
    u64 v;
    asm("ld.shared.b64 %0, [%1];" : "=l"(v) : "r"(addr));
    return v;
}
// butterfly-16 exchange of a packed u64 (two 32-bit shfls)
__device__ __forceinline__ u64 shfl16(u64 v) {
    u64 r;
    asm("{\n\t"
        ".reg .b32 a, b;\n\t"
        "mov.b64 {a, b}, %1;\n\t"
        "shfl.sync.bfly.b32 a, a, 16, 0x1f, 0xffffffff;\n\t"
        "shfl.sync.bfly.b32 b, b, 16, 0x1f, 0xffffffff;\n\t"
        "mov.b64 %0, {a, b};\n\t"
        "}" : "=l"(r) : "l"(v));
    return r;
}
__device__ __forceinline__ float ex2f(float x) {
    float r; asm("ex2.approx.f32 %0, %1;" : "=f"(r) : "f"(x)); return r;
}
__device__ __forceinline__ float rcpf(float x) {
    float r; asm("rcp.approx.f32 %0, %1;" : "=f"(r) : "f"(x)); return r;
}
__device__ __forceinline__ float sigmoidf(float x) {
    float t = ex2f(-1.4426950408889634f * x);
    return rcpf(1.0f + t);
}
__device__ __forceinline__ float tanhf_(float x) {
    float u = ex2f(-2.8853900817779268f * x);
    float r = rcpf(1.0f + u);
    return fmaf(-u, r, r);
}

// Shared layouts (identical to R5):
//  sW [P][kp][r], P=0..15 unit pair, r=gate*2+par, row j=(r>>1)*32+2P+(r&1)
//  sIn[P][r][s] : s=0 -> (W_ih[j][0], W_ih[j][1]) ; s=1 -> (b[j], 0)
//  sFC[n][kp]   : (W_fc[n][2kp], W_fc[n][2kp+1]);  sFCb[n] = (b_fc[n], 0)

__global__ void __launch_bounds__(THREADS, 2)
lstm_fused_kernel(const float* __restrict__ x,
                  const float* __restrict__ W_ih,
                  const float* __restrict__ W_hh,
                  const float* __restrict__ b_ih,
                  const float* __restrict__ b_hh,
                  const float* __restrict__ W_fc,
                  const float* __restrict__ b_fc,
                  float* __restrict__ out) {
    __shared__ __align__(16) u64 sW[16 * 16 * 8];
    __shared__ __align__(16) u64 sIn[16 * 8 * 2];
    __shared__ __align__(16) u64 sFC[2 * 16];
    __shared__ __align__(16) u64 sFCb[2];

    for (int i = threadIdx.x; i < 16 * 16 * 8; i += THREADS) {
        int r = i & 7, kp = (i >> 3) & 15, P = i >> 7;
        int j = (r >> 1) * 32 + 2 * P + (r & 1);
        sW[i] = pk(W_hh[j * 32 + 2 * kp], W_hh[j * 32 + 2 * kp + 1]);
    }
    for (int i = threadIdx.x; i < 16 * 8 * 2; i += THREADS) {
        int s = i & 1, r = (i >> 1) & 7, P = i >> 4;
        int j = (r >> 1) * 32 + 2 * P + (r & 1);
        sIn[i] = s ? pk(b_ih[j] + b_hh[j], 0.0f)
                   : pk(W_ih[2 * j], W_ih[2 * j + 1]);
    }
    for (int i = threadIdx.x; i < 32; i += THREADS) {
        int n = i >> 4, kp = i & 15;
        sFC[i] = pk(W_fc[n * 32 + 2 * kp], W_fc[n * 32 + 2 * kp + 1]);
    }
    if (threadIdx.x < 2) sFCb[threadIdx.x] = pk(b_fc[threadIdx.x], 0.0f);
    __syncthreads();

    const unsigned sW_a  = (unsigned)__cvta_generic_to_shared(sW);
    const unsigned sIn_a = (unsigned)__cvta_generic_to_shared(sIn);
    const unsigned sFC_a = (unsigned)__cvta_generic_to_shared(sFC);
    const unsigned sFCb_a = (unsigned)__cvta_generic_to_shared(sFCb);

    // lane pairing: lanes L and L^16 share the same 2 elements.
    const int lane  = threadIdx.x & 31;
    const int half  = lane >> 4;             // which unit-half this lane owns
    const int slot  = ((blockIdx.x * THREADS + threadIdx.x) >> 5) * 16
                      + (lane & 15);         // element pair id
    const int e0 = slot * 2;                 // elements e0, e0+1

    const float2* x2 = reinterpret_cast<const float2*>(x);
    u64 d0[2], d1[2], d2[2];
#pragma unroll
    for (int u = 0; u < 2; u++) {
        float2 v0 = x2[0 * BATCH + e0 + u];
        float2 v1 = x2[1 * BATCH + e0 + u];
        float2 v2 = x2[2 * BATCH + e0 + u];
        d0[u] = pk(v0.x, v0.y);
        d1[u] = pk(v1.x, v1.y);
        d2[u] = pk(v2.x, v2.y);
    }

    // h full (both halves, needed for dot products); c & hn own half only.
    u64 h2[2][16], hn[2][8], c2[2][8];
#pragma unroll
    for (int u = 0; u < 2; u++) {
#pragma unroll
        for (int k = 0; k < 16; k++) h2[u][k] = 0ull;
#pragma unroll
        for (int k = 0; k < 8; k++) c2[u][k] = 0ull;
    }

    const unsigned halfOffW = (unsigned)half * 8 * 1024;  // 8 P-slots * 1KB
    const unsigned halfOffI = (unsigned)half * 8 * 128;

    float2* o2 = reinterpret_cast<float2*>(out);

#pragma unroll 1
    for (int f = 0; f < FOUT; f++) {
#pragma unroll 1
        for (int t = 0; t < SEQB; t++) {
            const unsigned wA = launder(sW_a) + halfOffW;
            const unsigned iA = launder(sIn_a) + halfOffI;
            u64 xp[2];
#pragma unroll
            for (int u = 0; u < 2; u++)
                xp[u] = (t == 0) ? d0[u] : ((t == 1) ? d1[u] : d2[u]);
#pragma unroll
            for (int p = 0; p < 8; p++) {       // own 8 unit pairs
                const unsigned wbase = wA + p * 1024;
                const unsigned ibase = iA + p * 128;
                u64 a[2][8];
#pragma unroll
                for (int r = 0; r < 8; r += 2) {
                    u64 wiha, biasa, wihb, biasb;
                    lds2(wiha, biasa, ibase + r * 16);
                    lds2(wihb, biasb, ibase + r * 16 + 16);
#pragma unroll
                    for (int u = 0; u < 2; u++) {
                        a[u][r]     = ffma2(xp[u], wiha, biasa);
                        a[u][r + 1] = ffma2(xp[u], wihb, biasb);
                    }
                }
#pragma unroll
                for (int kp = 0; kp < 16; kp++) {
                    const unsigned ka = wbase + kp * 64;
                    u64 w0, w1, w2, w3;
                    lds2(w0, w1, ka);
                    lds2(w2, w3, ka + 16);
#pragma unroll
                    for (int u = 0; u < 2; u++) {
                        u64 hh = h2[u][kp];
                        a[u][0] = ffma2(hh, w0, a[u][0]);
                        a[u][1] = ffma2(hh, w1, a[u][1]);
                        a[u][2] = ffma2(hh, w2, a[u][2]);
                        a[u][3] = ffma2(hh, w3, a[u][3]);
                    }
                    lds2(w0, w1, ka + 32);
                    lds2(w2, w3, ka + 48);
#pragma unroll
                    for (int u = 0; u < 2; u++) {
                        u64 hh = h2[u][kp];
                        a[u][4] = ffma2(hh, w0, a[u][4]);
                        a[u][5] = ffma2(hh, w1, a[u][5]);
                        a[u][6] = ffma2(hh, w2, a[u][6]);
                        a[u][7] = ffma2(hh, w3, a[u][7]);
                    }
                }
#pragma unroll
                for (int u = 0; u < 2; u++) {
                    float lo, hi;
                    upk(a[u][0], lo, hi); float gi0 = sigmoidf(lo + hi);
                    upk(a[u][1], lo, hi); float gi1 = sigmoidf(lo + hi);
                    upk(a[u][2], lo, hi); float gf0 = sigmoidf(lo + hi);
                    upk(a[u][3], lo, hi); float gf1 = sigmoidf(lo + hi);
                    upk(a[u][4], lo, hi); float gg0 = tanhf_(lo + hi);
                    upk(a[u][5], lo, hi); float gg1 = tanhf_(lo + hi);
                    upk(a[u][6], lo, hi); float go0 = sigmoidf(lo + hi);
                    upk(a[u][7], lo, hi); float go1 = sigmoidf(lo + hi);
                    float c0, c1;
                    upk(c2[u][p], c0, c1);
                    float cn0 = fmaf(gf0, c0, gi0 * gg0);
                    float cn1 = fmaf(gf1, c1, gi1 * gg1);
                    c2[u][p] = pk(cn0, cn1);
                    hn[u][p] = pk(go0 * tanhf_(cn0), go1 * tanhf_(cn1));
                }
            }
            // commit: own half direct, partner half via bfly-16 exchange
#pragma unroll
            for (int u = 0; u < 2; u++) {
#pragma unroll
                for (int j = 0; j < 8; j++) {
                    u64 other = shfl16(hn[u][j]);
                    if (half == 0) {
                        h2[u][j]     = hn[u][j];
                        h2[u][8 + j] = other;
                    } else {
                        h2[u][8 + j] = hn[u][j];
                        h2[u][j]     = other;
                    }
                }
            }
        }
        // FC head (both lanes compute — result feeds the window; half 0 stores)
        const unsigned fA  = launder(sFC_a);
        const unsigned fbA = launder(sFCb_a);
        u64 acc0[2], acc1[2];
#pragma unroll
        for (int u = 0; u < 2; u++) {
            acc0[u] = lds1(fbA);
            acc1[u] = lds1(fbA + 8);
        }
#pragma unroll
        for (int kp = 0; kp < 16; kp += 2) {
            u64 w0, w1, w2, w3;
            lds2(w0, w1, fA + kp * 8);
            lds2(w2, w3, fA + 128 + kp * 8);
#pragma unroll
            for (int u = 0; u < 2; u++) {
                acc0[u] = ffma2(h2[u][kp], w0, acc0[u]);
                acc0[u] = ffma2(h2[u][kp + 1], w1, acc0[u]);
                acc1[u] = ffma2(h2[u][kp], w2, acc1[u]);
                acc1[u] = ffma2(h2[u][kp + 1], w3, acc1[u]);
            }
        }
#pragma unroll
        for (int u = 0; u < 2; u++) {
            float p0, q0, p1, q1;
            upk(acc0[u], p0, q0);
            upk(acc1[u], p1, q1);
            float out0 = p0 + q0;
            float out1 = p1 + q1;
            if (half == 0)
                o2[f * BATCH + e0 + u] = make_float2(out0, out1);
            // window update: data <- [data[2], data[1], output]
            d0[u] = d2[u];
            d2[u] = pk(out0, out1);
        }
    }
}

extern "C" void kernel_launch(void* const* d_in, const int* in_sizes, int n_in,
                              void* d_out, int out_size) {
    const float* x    = (const float*)d_in[0];
    const float* W_ih = (const float*)d_in[1];
    const float* W_hh = (const float*)d_in[2];
    const float* b_ih = (const float*)d_in[3];
    const float* b_hh = (const float*)d_in[4];
    const float* W_fc = (const float*)d_in[5];
    const float* b_fc = (const float*)d_in[6];
    float* out = (float*)d_out;

    dim3 grid(BATCH / THREADS);   // 2 lanes x half-units each -> 1 elem/thread equiv
    lstm_fused_kernel<<<grid, THREADS>>>(x, W_ih, W_hh, b_ih, b_hh, W_fc, b_fc, out);
}